// round 1
// baseline (speedup 1.0000x reference)
#include <cuda_runtime.h>

#define NF 32
#define NP 496
#define NU (NP + NF)          // 528 units total
#define NE 32
#define NH 64
#define FS 64
#define BATCH 2048
#define BT 256                // batch tile per block
#define TPAD 66               // padded row length for gather tables

// ---------------- device scratch (static allocation is allowed) ----------------
__device__ float g_T1[NP * FS * NH];   // layer0 table for first member of pair (+b0)
__device__ float g_T2[NP * FS * NH];   // layer0 table for second member of pair
__device__ float g_Tm[NF * FS * NH];   // layer0 table for main effects (+b0)
__device__ float g_gw2p[NP * NH];      // pw2 * smooth_z(z_pairs)
__device__ float g_gw2m[NF * NH];      // mw2 * smooth_z(z_main)
__device__ float g_C;                  // constant bias term (layer-2 biases * gates)

__device__ __forceinline__ float smoothz(float z) {
    if (z <= -0.5f) return 0.0f;
    if (z >= 0.5f) return 1.0f;
    return -2.0f * z * z * z + 1.5f * z + 0.5f;
}

// ---------------- kernel 1: precompute layer-0 lookup tables ----------------
// grid.x: [0,496) -> T1, [496,992) -> T2, [992,1024) -> Tm.  256 threads.
__global__ __launch_bounds__(256) void precompute_tables(
    const float* __restrict__ emb,
    const int* __restrict__ pairs_list,
    const int* __restrict__ offsets,
    const float* __restrict__ pw0, const float* __restrict__ pb0,
    const float* __restrict__ mw0, const float* __restrict__ mb0)
{
    __shared__ float Es[FS * NE];   // 64 x 32 embedding rows
    __shared__ float Ws[NE * NH];   // 32 x 64 weight slice

    int bid = blockIdx.x;
    int tid = threadIdx.x;

    const float* wsrc;
    const float* bias = nullptr;
    float* dst;
    int embRow0;

    if (bid < NP) {                       // T1: first half of pw0, + bias
        int p = bid;
        embRow0 = offsets[pairs_list[2 * p]];
        wsrc = pw0 + (p * 64 + 0) * NH;
        bias = pb0 + p * NH;
        dst = g_T1 + p * FS * NH;
    } else if (bid < 2 * NP) {            // T2: second half of pw0, no bias
        int p = bid - NP;
        embRow0 = offsets[pairs_list[2 * p + 1]];
        wsrc = pw0 + (p * 64 + 32) * NH;
        dst = g_T2 + p * FS * NH;
    } else {                              // Tm: main effect, + bias
        int f = bid - 2 * NP;
        embRow0 = f * FS;
        wsrc = mw0 + f * NE * NH;
        bias = mb0 + f * NH;
        dst = g_Tm + f * FS * NH;
    }

    for (int i = tid; i < FS * NE; i += 256) Es[i] = emb[embRow0 * NE + i];
    for (int i = tid; i < NE * NH; i += 256) Ws[i] = wsrc[i];
    __syncthreads();

    // each thread computes 16 outputs: row v = tid/4, cols j0..j0+15
    int v = tid >> 2;
    int j0 = (tid & 3) * 16;
    float acc[16];
#pragma unroll
    for (int t = 0; t < 16; t++) acc[t] = bias ? bias[j0 + t] : 0.0f;
    for (int e = 0; e < NE; e++) {
        float a = Es[v * NE + e];
#pragma unroll
        for (int t = 0; t < 16; t++) acc[t] = fmaf(a, Ws[e * NH + j0 + t], acc[t]);
    }
#pragma unroll
    for (int t = 0; t < 16; t++) dst[v * NH + j0 + t] = acc[t];
}

// ---------------- kernel 2: gated layer-2 weights + bias constant ----------------
__global__ void precompute_gates(
    const float* __restrict__ pw2, const float* __restrict__ pb2, const float* __restrict__ zp,
    const float* __restrict__ mw2, const float* __restrict__ mb2, const float* __restrict__ zm)
{
    int i = blockIdx.x * 256 + threadIdx.x;
    if (i < NP * NH) g_gw2p[i] = pw2[i] * smoothz(zp[i >> 6]);
    if (i < NF * NH) g_gw2m[i] = mw2[i] * smoothz(zm[i >> 6]);
    if (i == 0) {
        float c = 0.0f;
        for (int p = 0; p < NP; p++) c += pb2[p] * smoothz(zp[p]);
        for (int f = 0; f < NF; f++) c += mb2[f] * smoothz(zm[f]);
        g_C = c;
    }
}

// ---------------- kernel 3: init output with constant ----------------
__global__ void init_out(float* __restrict__ out) {
    out[blockIdx.x * 256 + threadIdx.x] = g_C;
}

// ---------------- kernel 4: fused main pass ----------------
// grid = (528 units, 8 batch tiles), 256 threads (1 sample per thread).
// dynamic smem layout: W1s[64*64] | T1s[64*TPAD] | T2s[64*TPAD] | b1s[64] | g2s[64]
#define SMEM_W1  0
#define SMEM_T1  (NH * NH)
#define SMEM_T2  (SMEM_T1 + FS * TPAD)
#define SMEM_B1  (SMEM_T2 + FS * TPAD)
#define SMEM_G2  (SMEM_B1 + NH)
#define SMEM_FLOATS (SMEM_G2 + NH)

__global__ __launch_bounds__(256) void fused_pass(
    const int* __restrict__ mains, const int* __restrict__ pairs,
    const float* __restrict__ pw1, const float* __restrict__ mw1,
    const float* __restrict__ pb1, const float* __restrict__ mb1,
    float* __restrict__ out)
{
    extern __shared__ float sm[];
    float* W1s = sm + SMEM_W1;
    float* T1s = sm + SMEM_T1;
    float* T2s = sm + SMEM_T2;
    float* b1s = sm + SMEM_B1;
    float* g2s = sm + SMEM_G2;

    int unit = blockIdx.x;
    int tile = blockIdx.y;
    int tid = threadIdx.x;
    bool isPair = unit < NP;

    const float *t1src, *t2src = nullptr, *w1src, *b1src, *g2src;
    if (isPair) {
        t1src = g_T1 + unit * FS * NH;
        t2src = g_T2 + unit * FS * NH;
        w1src = pw1 + unit * NH * NH;
        b1src = pb1 + unit * NH;
        g2src = g_gw2p + unit * NH;
    } else {
        int f = unit - NP;
        t1src = g_Tm + f * FS * NH;
        w1src = mw1 + f * NH * NH;
        b1src = mb1 + f * NH;
        g2src = g_gw2m + f * NH;
    }

    // ---- stage weights/tables into shared ----
    {
        const float2* s1 = (const float2*)t1src;
        for (int i = tid; i < FS * NH / 2; i += 256) {
            int v = i >> 5, j = i & 31;
            *(float2*)&T1s[v * TPAD + 2 * j] = s1[i];
        }
        if (isPair) {
            const float2* s2 = (const float2*)t2src;
            for (int i = tid; i < FS * NH / 2; i += 256) {
                int v = i >> 5, j = i & 31;
                *(float2*)&T2s[v * TPAD + 2 * j] = s2[i];
            }
        }
        const float4* sw = (const float4*)w1src;
        for (int i = tid; i < NH * NH / 4; i += 256) ((float4*)W1s)[i] = sw[i];
        if (tid < NH) { b1s[tid] = b1src[tid]; g2s[tid] = g2src[tid]; }
    }
    __syncthreads();

    int b = tile * BT + tid;

    // ---- layer 0: table lookup + add + relu ----
    float h0[NH];
    if (isPair) {
        int2 ii = ((const int2*)pairs)[b * NP + unit];
        const float* r1 = &T1s[ii.x * TPAD];
        const float* r2 = &T2s[ii.y * TPAD];
#pragma unroll
        for (int j = 0; j < NH; j += 2) {
            float2 a = *(const float2*)&r1[j];
            float2 c = *(const float2*)&r2[j];
            h0[j]     = fmaxf(a.x + c.x, 0.0f);
            h0[j + 1] = fmaxf(a.y + c.y, 0.0f);
        }
    } else {
        int i1 = mains[b * NF + (unit - NP)];
        const float* r1 = &T1s[i1 * TPAD];
#pragma unroll
        for (int j = 0; j < NH; j += 2) {
            float2 a = *(const float2*)&r1[j];
            h0[j]     = fmaxf(a.x, 0.0f);
            h0[j + 1] = fmaxf(a.y, 0.0f);
        }
    }

    // ---- layer 1 (64x64 matvec, weights broadcast from smem) + gated layer 2 ----
    float result = 0.0f;
#pragma unroll 1
    for (int j4 = 0; j4 < NH; j4 += 4) {
        float4 acc = *(const float4*)&b1s[j4];
#pragma unroll
        for (int k = 0; k < NH; k++) {
            float4 w = *(const float4*)&W1s[k * NH + j4];
            acc.x = fmaf(h0[k], w.x, acc.x);
            acc.y = fmaf(h0[k], w.y, acc.y);
            acc.z = fmaf(h0[k], w.z, acc.z);
            acc.w = fmaf(h0[k], w.w, acc.w);
        }
        float4 g = *(const float4*)&g2s[j4];
        result = fmaf(fmaxf(acc.x, 0.0f), g.x, result);
        result = fmaf(fmaxf(acc.y, 0.0f), g.y, result);
        result = fmaf(fmaxf(acc.z, 0.0f), g.z, result);
        result = fmaf(fmaxf(acc.w, 0.0f), g.w, result);
    }

    atomicAdd(&out[b], result);
}

// ---------------- launch ----------------
extern "C" void kernel_launch(void* const* d_in, const int* in_sizes, int n_in,
                              void* d_out, int out_size)
{
    const int*   mains      = (const int*)d_in[0];
    const int*   pairs      = (const int*)d_in[1];
    const int*   pairs_list = (const int*)d_in[2];
    const int*   offsets    = (const int*)d_in[3];
    const float* embedding  = (const float*)d_in[4];
    const float* mw0        = (const float*)d_in[5];
    const float* mw1        = (const float*)d_in[6];
    const float* mw2        = (const float*)d_in[7];
    const float* mb0        = (const float*)d_in[8];
    const float* mb1        = (const float*)d_in[9];
    const float* mb2        = (const float*)d_in[10];
    const float* pw0        = (const float*)d_in[11];
    const float* pw1        = (const float*)d_in[12];
    const float* pw2        = (const float*)d_in[13];
    const float* pb0        = (const float*)d_in[14];
    const float* pb1        = (const float*)d_in[15];
    const float* pb2        = (const float*)d_in[16];
    const float* z_main     = (const float*)d_in[17];
    const float* z_pairs    = (const float*)d_in[18];
    float* out = (float*)d_out;

    static int smem_attr_set = 0;
    const int smem_bytes = SMEM_FLOATS * (int)sizeof(float);
    if (!smem_attr_set) {
        cudaFuncSetAttribute(fused_pass, cudaFuncAttributeMaxDynamicSharedMemorySize, smem_bytes);
        smem_attr_set = 1;
    }

    precompute_tables<<<2 * NP + NF, 256>>>(embedding, pairs_list, offsets,
                                            pw0, pb0, mw0, mb0);
    precompute_gates<<<(NP * NH + 255) / 256, 256>>>(pw2, pb2, z_pairs, mw2, mb2, z_main);
    init_out<<<BATCH / 256, 256>>>(out);

    dim3 grid(NU, BATCH / BT);
    fused_pass<<<grid, 256, smem_bytes>>>(mains, pairs, pw1, mw1, pb1, mb1, out);
}